// round 16
// baseline (speedup 1.0000x reference)
#include <cuda_runtime.h>
#include <cuda_bf16.h>
#include <cstdint>

// Round 16: scan widened to 512 threads (1 gate column per thread, FULL k,
// 4 warps/SMSP), single-level 8-shuffle epilogue, 1 barrier/step, permuted
// pre layout for coalesced per-thread loads. GEMM: persistent (R15) with
// permuted stores.

#define BB 256
#define SS 2048
#define II 64
#define HH 128
#define GG 512
#define NCTA 128
#define SCAN_THR 512
#define GEMM_CTAS 148
#define TOT_TILES ((BB * SS) / 64)      // 8192

#define REG_K 72                        // reg k-rows (36 u64 pairs)
#define SMK   56                        // smem k-rows
#define PTS   (SMK + 4)                 // 60 floats: 15 float4s (odd -> conflict-free)
#define SW_FLOATS (SCAN_THR * PTS)
#define SCAN_SMEM_BYTES ((SW_FLOATS + 2 * 256) * 4)

#define ARS 36
#define OFF_AH 0
#define OFF_AL (64 * ARS)
#define OFF_BH (2 * 64 * ARS)
#define OFF_BL (OFF_BH + 512 * ARS)
#define PROD_UINTS (OFF_BL + 512 * ARS)
#define GEMM_SMEM_BYTES (PROD_UINTS * 4)

typedef unsigned long long u64;

__device__ float g_pre[(long long)BB * SS * GG];          // 1 GB scratch (permuted cols)
__device__ __align__(16) unsigned g_wh[GG * II / 2];
__device__ __align__(16) unsigned g_wl[GG * II / 2];

__device__ __forceinline__ u64 ffma2(u64 a, u64 b, u64 c) {
    u64 d;
    asm("fma.rn.f32x2 %0, %1, %2, %3;" : "=l"(d) : "l"(a), "l"(b), "l"(c));
    return d;
}
__device__ __forceinline__ u64 packf2(float lo, float hi) {
    u64 r;
    asm("mov.b64 %0, {%1, %2};" : "=l"(r) : "f"(lo), "f"(hi));
    return r;
}
__device__ __forceinline__ float2 unpackf2(u64 v) {
    float2 r;
    asm("mov.b64 {%0, %1}, %2;" : "=f"(r.x), "=f"(r.y) : "l"(v));
    return r;
}
__device__ __forceinline__ float fast_tanh(float x) {
    float xc = fminf(fmaxf(x, -12.0f), 12.0f);
    float e  = __expf(2.0f * xc);
    return __fdividef(e - 1.0f, e + 1.0f);
}
__device__ __forceinline__ unsigned pack_bf16_hi(float a, float b) {
    __nv_bfloat16 ah = __float2bfloat16(a), bh = __float2bfloat16(b);
    return (unsigned)__bfloat16_as_ushort(ah) | ((unsigned)__bfloat16_as_ushort(bh) << 16);
}
__device__ __forceinline__ unsigned pack_bf16_lo(float a, float b) {
    __nv_bfloat16 ah = __float2bfloat16(a), bh = __float2bfloat16(b);
    __nv_bfloat16 al = __float2bfloat16(a - __bfloat162float(ah));
    __nv_bfloat16 bl = __float2bfloat16(b - __bfloat162float(bh));
    return (unsigned)__bfloat16_as_ushort(al) | ((unsigned)__bfloat16_as_ushort(bl) << 16);
}
__device__ __forceinline__ void mma16816(float* c, const unsigned* a,
                                         unsigned b0, unsigned b1) {
    asm volatile(
        "mma.sync.aligned.m16n8k16.row.col.f32.bf16.bf16.f32 "
        "{%0,%1,%2,%3}, {%4,%5,%6,%7}, {%8,%9}, {%0,%1,%2,%3};"
        : "+f"(c[0]), "+f"(c[1]), "+f"(c[2]), "+f"(c[3])
        : "r"(a[0]), "r"(a[1]), "r"(a[2]), "r"(a[3]), "r"(b0), "r"(b1));
}
// column permutation: scan thread tid = w*32+l owns col c = 16l+w; perm(c)=tid
__device__ __forceinline__ int perm_col(int n) {
    return ((n & 15) << 5) + (n >> 4);
}

__global__ void prep_w_kernel(const float* __restrict__ Wm) {
    int i = blockIdx.x * 256 + threadIdx.x;       // 16384 pairs
    float a = Wm[2 * i], b = Wm[2 * i + 1];
    g_wh[i] = pack_bf16_hi(a, b);
    g_wl[i] = pack_bf16_lo(a, b);
}

// ---------------------------------------------------------------------------
// Persistent GEMM (R15) with permuted column stores.
// ---------------------------------------------------------------------------
__global__ void __launch_bounds__(256, 1)
pre_gemm_persist(const float* __restrict__ xg, float* __restrict__ pre)
{
    extern __shared__ unsigned usm[];
    unsigned* Ah = usm + OFF_AH;
    unsigned* Al = usm + OFF_AL;
    unsigned* Bh = usm + OFF_BH;
    unsigned* Bl = usm + OFF_BL;
    const int tid = threadIdx.x;

#pragma unroll
    for (int j = 0; j < 16; j++) {
        int idx = tid + j * 256;
        int n = idx >> 3, kq = idx & 7;
        uint4 hv = ((const uint4*)g_wh)[idx];
        uint4 lv = ((const uint4*)g_wl)[idx];
        *(uint4*)(Bh + n * ARS + kq * 4) = hv;
        *(uint4*)(Bl + n * ARS + kq * 4) = lv;
    }

    const int w    = tid >> 5;
    const int lane = tid & 31;
    const int gid  = lane >> 2;
    const int tig  = lane & 3;
    const int mg   = w >> 2;
    const int ng   = w & 3;

    float2 areg[8];
    long long tile = blockIdx.x;
    {
        const float* xt = xg + tile * 64 * II;
#pragma unroll
        for (int j = 0; j < 8; j++) {
            int idx = tid + j * 256;
            areg[j] = __ldg((const float2*)(xt + (idx >> 5) * II + (idx & 31) * 2));
        }
    }

#pragma unroll 1
    for (; tile < TOT_TILES; tile += GEMM_CTAS) {
        __syncthreads();
#pragma unroll
        for (int j = 0; j < 8; j++) {
            int idx = tid + j * 256;
            int row = idx >> 5, kp = idx & 31;
            Ah[row * ARS + kp] = pack_bf16_hi(areg[j].x, areg[j].y);
            Al[row * ARS + kp] = pack_bf16_lo(areg[j].x, areg[j].y);
        }
        __syncthreads();

        long long nxt = tile + GEMM_CTAS;
        if (nxt < TOT_TILES) {
            const float* xt = xg + nxt * 64 * II;
#pragma unroll
            for (int j = 0; j < 8; j++) {
                int idx = tid + j * 256;
                areg[j] = __ldg((const float2*)(xt + (idx >> 5) * II + (idx & 31) * 2));
            }
        }

        float acc[2][16][4];
#pragma unroll
        for (int mt = 0; mt < 2; mt++)
#pragma unroll
            for (int nc = 0; nc < 16; nc++)
#pragma unroll
                for (int e = 0; e < 4; e++) acc[mt][nc][e] = 0.0f;

#pragma unroll
        for (int ks = 0; ks < 4; ks++) {
            unsigned ah[2][4], al[2][4];
#pragma unroll
            for (int mt = 0; mt < 2; mt++) {
                int r0 = mg * 32 + mt * 16 + gid;
                int ui = ks * 8 + tig;
                ah[mt][0] = Ah[r0 * ARS + ui];
                ah[mt][1] = Ah[(r0 + 8) * ARS + ui];
                ah[mt][2] = Ah[r0 * ARS + ui + 4];
                ah[mt][3] = Ah[(r0 + 8) * ARS + ui + 4];
                al[mt][0] = Al[r0 * ARS + ui];
                al[mt][1] = Al[(r0 + 8) * ARS + ui];
                al[mt][2] = Al[r0 * ARS + ui + 4];
                al[mt][3] = Al[(r0 + 8) * ARS + ui + 4];
            }
#pragma unroll
            for (int nc = 0; nc < 16; nc++) {
                int n  = ng * 128 + nc * 8 + gid;
                int ui = ks * 8 + tig;
                unsigned bh0 = Bh[n * ARS + ui];
                unsigned bh1 = Bh[n * ARS + ui + 4];
                unsigned bl0 = Bl[n * ARS + ui];
                unsigned bl1 = Bl[n * ARS + ui + 4];
#pragma unroll
                for (int mt = 0; mt < 2; mt++) {
                    mma16816(acc[mt][nc], ah[mt], bh0, bh1);
                    mma16816(acc[mt][nc], al[mt], bh0, bh1);
                    mma16816(acc[mt][nc], ah[mt], bl0, bl1);
                }
            }
        }
        long long mbase = tile * 64;
#pragma unroll
        for (int mt = 0; mt < 2; mt++) {
#pragma unroll
            for (int nc = 0; nc < 16; nc++) {
                long long m = mbase + mg * 32 + mt * 16 + gid;
                int n = ng * 128 + nc * 8 + tig * 2;
                int pa0 = perm_col(n);
                int pa1 = perm_col(n + 1);
                pre[m * GG + pa0]       = acc[mt][nc][0];
                pre[m * GG + pa1]       = acc[mt][nc][1];
                pre[(m + 8) * GG + pa0] = acc[mt][nc][2];
                pre[(m + 8) * GG + pa1] = acc[mt][nc][3];
            }
        }
    }
}

// ---------------------------------------------------------------------------
// scan: 512 threads; thread (w,l) owns col c = 16l + w (full k), both rows.
// 4 FFMA2 chains; single-level 8-shuffle gate gather; 1 barrier/step.
// ---------------------------------------------------------------------------
__global__ void __launch_bounds__(SCAN_THR, 1)
slstm_scan_kernel(const float* __restrict__ pre, const float* __restrict__ Rm,
                  const float* __restrict__ bias, float* __restrict__ out)
{
    extern __shared__ float smem[];
    float* sW = smem;                    // [512][PTS]
    float* hb = smem + SW_FLOATS;        // [2][2][HH]

    const int tid = threadIdx.x;
    const int w   = tid >> 5;            // 0..15
    const int l   = tid & 31;
    const int c   = 16 * l + w;          // owned gate column
    const int b0  = blockIdx.x * 2;

    // register weights: R rows [0, REG_K), packed k-pairs for col c
    u64 wp[REG_K / 2];
#pragma unroll
    for (int j = 0; j < REG_K / 2; j++)
        wp[j] = packf2(Rm[(2 * j) * GG + c], Rm[(2 * j + 1) * GG + c]);
    // smem weights: rows [REG_K, 128), slab[kc] = R[REG_K+kc][c]
    {
        float* slab = sW + tid * PTS;
#pragma unroll
        for (int kc = 0; kc < SMK; kc++)
            slab[kc] = Rm[(REG_K + kc) * GG + c];
    }
    const float bg = bias[c];

    hb[tid & 511] = 0.0f;                // covers both buffers (512 floats)
    __syncthreads();

    const float* pr0 = pre + (long long)(b0)     * SS * GG;
    const float* pr1 = pre + (long long)(b0 + 1) * SS * GG;

    float p0 = __ldg(pr0 + tid);         // permuted: col c lives at offset tid
    float p1 = __ldg(pr1 + tid);

    const int j7    = l & 7;
    const int row_e = (l >> 3) & 1;      // lanes 0-7 row0, 8-15 row1, 16-31 dup
    const int hid   = 16 * j7 + w;
    float c_ = 0.0f, n_ = 0.0f, m_ = 0.0f;

    const float* sWg = sW + tid * PTS;

    // deferred coalesced out write mapping (tid < 256)
    const int orow = tid >> 7;
    const int ohid = tid & 127;
    float* outp = out + ((long long)(b0 + orow) * SS) * HH + ohid;

#pragma unroll 1
    for (int step = 0; step < SS; step++) {
        const float* h0 = hb + (step & 1) * 256;
        const float* h1 = h0 + HH;
        float* hn = hb + ((step + 1) & 1) * 256;

        // write out[step-1] from the buffer holding h(step) (coalesced)
        if (step > 0 && tid < 256)
            outp[(long long)(step - 1) * HH] = h0[tid];

        float q0 = 0.f, q1 = 0.f;
        if (step + 1 < SS) {
            long long off = (long long)(step + 1) * GG + tid;
            q0 = __ldg(pr0 + off);
            q1 = __ldg(pr1 + off);
        }

        u64 a0a = 0, a0b = 0, a1a = 0, a1b = 0;   // 4 chains

#pragma unroll
        for (int i = 0; i < REG_K / 4; i++) {     // 18 iters
            ulonglong2 hp0 = *(const ulonglong2*)(h0 + 4 * i);
            ulonglong2 hp1 = *(const ulonglong2*)(h1 + 4 * i);
            a0a = ffma2(hp0.x, wp[2 * i],     a0a);
            a0b = ffma2(hp0.y, wp[2 * i + 1], a0b);
            a1a = ffma2(hp1.x, wp[2 * i],     a1a);
            a1b = ffma2(hp1.y, wp[2 * i + 1], a1b);
        }
#pragma unroll
        for (int i = 0; i < SMK / 4; i++) {       // 14 iters
            ulonglong2 wv  = *(const ulonglong2*)(sWg + 4 * i);
            ulonglong2 hp0 = *(const ulonglong2*)(h0 + REG_K + 4 * i);
            ulonglong2 hp1 = *(const ulonglong2*)(h1 + REG_K + 4 * i);
            a0a = ffma2(hp0.x, wv.x, a0a);
            a0b = ffma2(hp0.y, wv.y, a0b);
            a1a = ffma2(hp1.x, wv.x, a1a);
            a1b = ffma2(hp1.y, wv.y, a1b);
        }

        float2 f0a = unpackf2(a0a), f0b = unpackf2(a0b);
        float2 f1a = unpackf2(a1a), f1b = unpackf2(a1b);
        float aa = (f0a.x + f0a.y) + (f0b.x + f0b.y) + p0 + bg;   // (row0, c)
        float bb = (f1a.x + f1a.y) + (f1b.x + f1b.y) + p1 + bg;   // (row1, c)

        // single-level gate gather: gate q of hid(16*j7+w) row r is in lane 8q+j7
        float sA0 = __shfl_sync(0xFFFFFFFFu, aa, j7);
        float sB0 = __shfl_sync(0xFFFFFFFFu, bb, j7);
        float sA1 = __shfl_sync(0xFFFFFFFFu, aa, 8 | j7);
        float sB1 = __shfl_sync(0xFFFFFFFFu, bb, 8 | j7);
        float sA2 = __shfl_sync(0xFFFFFFFFu, aa, 16 | j7);
        float sB2 = __shfl_sync(0xFFFFFFFFu, bb, 16 | j7);
        float sA3 = __shfl_sync(0xFFFFFFFFu, aa, 24 | j7);
        float sB3 = __shfl_sync(0xFFFFFFFFu, bb, 24 | j7);
        float iv = row_e ? sB0 : sA0;
        float fv = row_e ? sB1 : sA1;
        float ov = row_e ? sB2 : sA2;
        float zv = row_e ? sB3 : sA3;

        // exponential-gating state update (lanes 16-31 duplicate, don't store)
        float tz = fast_tanh(zv);
        float so = __fdividef(1.0f, 1.0f + __expf(-ov));
        float lf = fminf(fv, 0.0f) - __logf(1.0f + __expf(-fabsf(fv)));
        float mn = fmaxf(lf + m_, iv);
        float ip = __expf(iv - mn);
        float fp = __expf(lf + m_ - mn);
        c_ = fp * c_ + ip * tz;
        n_ = fp * n_ + ip;
        m_ = mn;
        float hv = so * fast_tanh(__fdividef(c_, n_));

        if (l < 16)
            hn[row_e * HH + hid] = hv;

        p0 = q0; p1 = q1;
        __syncthreads();
    }

    // final step's output: h(SS) sits in buffer (SS & 1) == 0
    if (tid < 256)
        outp[(long long)(SS - 1) * HH] = hb[(SS & 1) * 256 + tid];
}

extern "C" void kernel_launch(void* const* d_in, const int* in_sizes, int n_in,
                              void* d_out, int out_size)
{
    const float* xg = (const float*)d_in[0];
    const float* Wm = (const float*)d_in[1];
    const float* Rm = (const float*)d_in[2];
    const float* bv = (const float*)d_in[3];
    if (n_in >= 3 && in_sizes[1] == HH * GG && in_sizes[2] == GG * II) {
        const float* t = Wm; Wm = Rm; Rm = t;
    }
    float* out = (float*)d_out;

    float* pre = nullptr;
    cudaGetSymbolAddress((void**)&pre, g_pre);

    cudaFuncSetAttribute(pre_gemm_persist,
                         cudaFuncAttributeMaxDynamicSharedMemorySize, GEMM_SMEM_BYTES);
    cudaFuncSetAttribute(slstm_scan_kernel,
                         cudaFuncAttributeMaxDynamicSharedMemorySize, SCAN_SMEM_BYTES);

    prep_w_kernel<<<64, 256>>>(Wm);
    pre_gemm_persist<<<GEMM_CTAS, 256, GEMM_SMEM_BYTES>>>(xg, pre);
    slstm_scan_kernel<<<NCTA, SCAN_THR, SCAN_SMEM_BYTES>>>(pre, Rm, bv, out);
}

// round 17
// speedup vs baseline: 1.5833x; 1.5833x over previous
#include <cuda_runtime.h>
#include <cuda_bf16.h>
#include <cstdint>

// Round 17: R15 structure (persistent HMMA GEMM -> fp32 FFMA2 scan) with the
// scan's serial epilogue chain shortened via HW tanh.approx.f32 (both tanhs +
// sigmoid), and the W->bf16 prep folded into the GEMM's B-load (one less
// kernel launch).

#define BB 256
#define SS 2048
#define II 64
#define HH 128
#define GG 512
#define NCTA 128
#define NTHR 256
#define GEMM_CTAS 148
#define TOT_TILES ((BB * SS) / 64)      // 8192

#define REG_K 96
#define SMK   32
#define PTS  (SMK * 2 + 4)              // 68 floats (proven conflict-free)
#define SW_FLOATS (NTHR * PTS)
#define HB_FLOATS (2 * 2 * HH)
#define SCAN_SMEM_BYTES ((SW_FLOATS + HB_FLOATS) * 4)

#define ARS 36
#define OFF_AH 0
#define OFF_AL (64 * ARS)
#define OFF_BH (2 * 64 * ARS)
#define OFF_BL (OFF_BH + 512 * ARS)
#define PROD_UINTS (OFF_BL + 512 * ARS)
#define GEMM_SMEM_BYTES (PROD_UINTS * 4)

typedef unsigned long long u64;

__device__ float g_pre[(long long)BB * SS * GG];          // 1 GB scratch

__device__ __forceinline__ u64 ffma2(u64 a, u64 b, u64 c) {
    u64 d;
    asm("fma.rn.f32x2 %0, %1, %2, %3;" : "=l"(d) : "l"(a), "l"(b), "l"(c));
    return d;
}
__device__ __forceinline__ u64 packf2(float lo, float hi) {
    u64 r;
    asm("mov.b64 %0, {%1, %2};" : "=l"(r) : "f"(lo), "f"(hi));
    return r;
}
__device__ __forceinline__ float2 unpackf2(u64 v) {
    float2 r;
    asm("mov.b64 {%0, %1}, %2;" : "=f"(r.x), "=f"(r.y) : "l"(v));
    return r;
}
__device__ __forceinline__ float tanh_hw(float x) {
    float y;
    asm("tanh.approx.f32 %0, %1;" : "=f"(y) : "f"(x));
    return y;
}
__device__ __forceinline__ unsigned pack_bf16_hi(float a, float b) {
    __nv_bfloat16 ah = __float2bfloat16(a), bh = __float2bfloat16(b);
    return (unsigned)__bfloat16_as_ushort(ah) | ((unsigned)__bfloat16_as_ushort(bh) << 16);
}
__device__ __forceinline__ unsigned pack_bf16_lo(float a, float b) {
    __nv_bfloat16 ah = __float2bfloat16(a), bh = __float2bfloat16(b);
    __nv_bfloat16 al = __float2bfloat16(a - __bfloat162float(ah));
    __nv_bfloat16 bl = __float2bfloat16(b - __bfloat162float(bh));
    return (unsigned)__bfloat16_as_ushort(al) | ((unsigned)__bfloat16_as_ushort(bl) << 16);
}
__device__ __forceinline__ void mma16816(float* c, const unsigned* a,
                                         unsigned b0, unsigned b1) {
    asm volatile(
        "mma.sync.aligned.m16n8k16.row.col.f32.bf16.bf16.f32 "
        "{%0,%1,%2,%3}, {%4,%5,%6,%7}, {%8,%9}, {%0,%1,%2,%3};"
        : "+f"(c[0]), "+f"(c[1]), "+f"(c[2]), "+f"(c[3])
        : "r"(a[0]), "r"(a[1]), "r"(a[2]), "r"(a[3]), "r"(b0), "r"(b1));
}

// ---------------------------------------------------------------------------
// Persistent GEMM: 148 CTAs; B converted fp32->bf16 hi/lo in-CTA and resident;
// next-A prefetched into regs under the current tile's HMMA.
// ---------------------------------------------------------------------------
__global__ void __launch_bounds__(NTHR, 1)
pre_gemm_persist(const float* __restrict__ xg, const float* __restrict__ Wm,
                 float* __restrict__ pre)
{
    extern __shared__ unsigned usm[];
    unsigned* Ah = usm + OFF_AH;
    unsigned* Al = usm + OFF_AL;
    unsigned* Bh = usm + OFF_BH;
    unsigned* Bl = usm + OFF_BL;
    const int tid = threadIdx.x;

    // ---- load + convert B once (W is 512x64 fp32, row-major) ----
#pragma unroll 4
    for (int j = 0; j < 64; j++) {
        int p = tid + j * 256;               // pair index, 16384 total
        int n = p >> 5, kp = p & 31;
        float2 v = __ldg((const float2*)(Wm + n * II + kp * 2));
        Bh[n * ARS + kp] = pack_bf16_hi(v.x, v.y);
        Bl[n * ARS + kp] = pack_bf16_lo(v.x, v.y);
    }

    const int w    = tid >> 5;
    const int lane = tid & 31;
    const int gid  = lane >> 2;
    const int tig  = lane & 3;
    const int mg   = w >> 2;
    const int ng   = w & 3;

    float2 areg[8];
    long long tile = blockIdx.x;
    {
        const float* xt = xg + tile * 64 * II;
#pragma unroll
        for (int j = 0; j < 8; j++) {
            int idx = tid + j * 256;
            areg[j] = __ldg((const float2*)(xt + (idx >> 5) * II + (idx & 31) * 2));
        }
    }

#pragma unroll 1
    for (; tile < TOT_TILES; tile += GEMM_CTAS) {
        __syncthreads();
#pragma unroll
        for (int j = 0; j < 8; j++) {
            int idx = tid + j * 256;
            int row = idx >> 5, kp = idx & 31;
            Ah[row * ARS + kp] = pack_bf16_hi(areg[j].x, areg[j].y);
            Al[row * ARS + kp] = pack_bf16_lo(areg[j].x, areg[j].y);
        }
        __syncthreads();

        long long nxt = tile + GEMM_CTAS;
        if (nxt < TOT_TILES) {
            const float* xt = xg + nxt * 64 * II;
#pragma unroll
            for (int j = 0; j < 8; j++) {
                int idx = tid + j * 256;
                areg[j] = __ldg((const float2*)(xt + (idx >> 5) * II + (idx & 31) * 2));
            }
        }

        float acc[2][16][4];
#pragma unroll
        for (int mt = 0; mt < 2; mt++)
#pragma unroll
            for (int nc = 0; nc < 16; nc++)
#pragma unroll
                for (int e = 0; e < 4; e++) acc[mt][nc][e] = 0.0f;

#pragma unroll
        for (int ks = 0; ks < 4; ks++) {
            unsigned ah[2][4], al[2][4];
#pragma unroll
            for (int mt = 0; mt < 2; mt++) {
                int r0 = mg * 32 + mt * 16 + gid;
                int ui = ks * 8 + tig;
                ah[mt][0] = Ah[r0 * ARS + ui];
                ah[mt][1] = Ah[(r0 + 8) * ARS + ui];
                ah[mt][2] = Ah[r0 * ARS + ui + 4];
                ah[mt][3] = Ah[(r0 + 8) * ARS + ui + 4];
                al[mt][0] = Al[r0 * ARS + ui];
                al[mt][1] = Al[(r0 + 8) * ARS + ui];
                al[mt][2] = Al[r0 * ARS + ui + 4];
                al[mt][3] = Al[(r0 + 8) * ARS + ui + 4];
            }
#pragma unroll
            for (int nc = 0; nc < 16; nc++) {
                int n  = ng * 128 + nc * 8 + gid;
                int ui = ks * 8 + tig;
                unsigned bh0 = Bh[n * ARS + ui];
                unsigned bh1 = Bh[n * ARS + ui + 4];
                unsigned bl0 = Bl[n * ARS + ui];
                unsigned bl1 = Bl[n * ARS + ui + 4];
#pragma unroll
                for (int mt = 0; mt < 2; mt++) {
                    mma16816(acc[mt][nc], ah[mt], bh0, bh1);
                    mma16816(acc[mt][nc], al[mt], bh0, bh1);
                    mma16816(acc[mt][nc], ah[mt], bl0, bl1);
                }
            }
        }
        long long mbase = tile * 64;
#pragma unroll
        for (int mt = 0; mt < 2; mt++) {
#pragma unroll
            for (int nc = 0; nc < 16; nc++) {
                long long m = mbase + mg * 32 + mt * 16 + gid;
                int n = ng * 128 + nc * 8 + tig * 2;
                *(float2*)(pre + m * GG + n)       = make_float2(acc[mt][nc][0], acc[mt][nc][1]);
                *(float2*)(pre + (m + 8) * GG + n) = make_float2(acc[mt][nc][2], acc[mt][nc][3]);
            }
        }
    }
}

// ---------------------------------------------------------------------------
// scan: round-7/15 body; epilogue uses HW tanh.approx (2x) and sigmoid via
// tanh. FFMA2 mainloop, shuffle epilogue, 1 barrier/step.
// ---------------------------------------------------------------------------
__global__ void __launch_bounds__(NTHR, 1)
slstm_scan_kernel(const float* __restrict__ pre, const float* __restrict__ Rm,
                  const float* __restrict__ bias, float* __restrict__ out)
{
    extern __shared__ float smem[];
    float* sW = smem;                    // [256][PTS]
    float* hb = smem + SW_FLOATS;        // [2][2][HH]

    const int tid = threadIdx.x;
    const int w   = tid >> 5;
    const int l   = tid & 31;
    const int c0  = 16 * l + 2 * w;
    const int c1  = c0 + 1;
    const int b0  = blockIdx.x * 2;

    u64 wp0[REG_K / 2], wp1[REG_K / 2];
#pragma unroll
    for (int j = 0; j < REG_K / 2; j++) {
        wp0[j] = packf2(Rm[(2 * j) * GG + c0], Rm[(2 * j + 1) * GG + c0]);
        wp1[j] = packf2(Rm[(2 * j) * GG + c1], Rm[(2 * j + 1) * GG + c1]);
    }
    {
        float* slab = sW + tid * PTS;
#pragma unroll
        for (int kc = 0; kc < SMK; kc += 4) {
            int k = REG_K + kc;
            slab[kc * 2 + 0] = Rm[(k + 0) * GG + c0];
            slab[kc * 2 + 1] = Rm[(k + 1) * GG + c0];
            slab[kc * 2 + 2] = Rm[(k + 0) * GG + c1];
            slab[kc * 2 + 3] = Rm[(k + 1) * GG + c1];
            slab[kc * 2 + 4] = Rm[(k + 2) * GG + c0];
            slab[kc * 2 + 5] = Rm[(k + 3) * GG + c0];
            slab[kc * 2 + 6] = Rm[(k + 2) * GG + c1];
            slab[kc * 2 + 7] = Rm[(k + 3) * GG + c1];
        }
    }
    const float bg0 = bias[c0];
    const float bg1 = bias[c1];

    hb[tid] = 0.0f;
    hb[tid + 256] = 0.0f;
    __syncthreads();

    const float* pr0 = pre + (long long)(b0)     * SS * GG;
    const float* pr1 = pre + (long long)(b0 + 1) * SS * GG;

    float2 p0 = __ldg((const float2*)(pr0 + c0));
    float2 p1 = __ldg((const float2*)(pr1 + c0));

    const int my_row = (l >> 4) & 1;
    const int my_hid = 16 * (l & 7) + 2 * w + ((l >> 3) & 1);
    float c_ = 0.0f, n_ = 0.0f, m_ = 0.0f;

    const bool lo16 = (l < 16);
    const bool b3   = ((l >> 3) & 1) != 0;
    const float* sWg = sW + tid * PTS;

    float* outp = out + ((long long)(b0 + my_row) * SS) * HH + my_hid;

#pragma unroll 1
    for (int step = 0; step < SS; step++) {
        const float* h0 = hb + (step & 1) * 256;
        const float* h1 = h0 + HH;
        float* hn = hb + ((step + 1) & 1) * 256;

        float2 q0 = make_float2(0.f, 0.f), q1 = make_float2(0.f, 0.f);
        if (step + 1 < SS) {
            long long off = (long long)(step + 1) * GG;
            q0 = __ldg((const float2*)(pr0 + off + c0));
            q1 = __ldg((const float2*)(pr1 + off + c0));
        }

        u64 a00 = 0, a10 = 0, a01 = 0, a11 = 0;

#pragma unroll
        for (int k = 0; k < REG_K; k += 4) {
            ulonglong2 hp0 = *(const ulonglong2*)(h0 + k);
            ulonglong2 hp1 = *(const ulonglong2*)(h1 + k);
            int j = k / 2;
            a00 = ffma2(hp0.x, wp0[j],     a00);
            a10 = ffma2(hp0.x, wp1[j],     a10);
            a01 = ffma2(hp1.x, wp0[j],     a01);
            a11 = ffma2(hp1.x, wp1[j],     a11);
            a00 = ffma2(hp0.y, wp0[j + 1], a00);
            a10 = ffma2(hp0.y, wp1[j + 1], a10);
            a01 = ffma2(hp1.y, wp0[j + 1], a01);
            a11 = ffma2(hp1.y, wp1[j + 1], a11);
        }
#pragma unroll
        for (int k = 0; k < SMK; k += 4) {
            ulonglong2 wv0 = *(const ulonglong2*)(sWg + k * 2);
            ulonglong2 wv1 = *(const ulonglong2*)(sWg + k * 2 + 4);
            ulonglong2 hp0 = *(const ulonglong2*)(h0 + REG_K + k);
            ulonglong2 hp1 = *(const ulonglong2*)(h1 + REG_K + k);
            a00 = ffma2(hp0.x, wv0.x, a00);
            a10 = ffma2(hp0.x, wv0.y, a10);
            a01 = ffma2(hp1.x, wv0.x, a01);
            a11 = ffma2(hp1.x, wv0.y, a11);
            a00 = ffma2(hp0.y, wv1.x, a00);
            a10 = ffma2(hp0.y, wv1.y, a10);
            a01 = ffma2(hp1.y, wv1.x, a01);
            a11 = ffma2(hp1.y, wv1.y, a11);
        }

        float2 t0 = unpackf2(a00), t1 = unpackf2(a10);
        float2 t2 = unpackf2(a01), t3 = unpackf2(a11);
        float aa = t0.x + t0.y + p0.x + bg0;
        float bb = t1.x + t1.y + p0.y + bg1;
        float cc = t2.x + t2.y + p1.x + bg0;
        float dd = t3.x + t3.y + p1.y + bg1;

        // warp-local gate transpose (4 shuffles)
        float u1 = lo16 ? cc : aa;
        float u2 = lo16 ? dd : bb;
        float r1v = __shfl_xor_sync(0xFFFFFFFFu, u1, 16);
        float r2v = __shfl_xor_sync(0xFFFFFFFFu, u2, 16);
        float Ag = lo16 ? aa : r1v;
        float Bg = lo16 ? bb : r2v;
        float Cg = lo16 ? r1v : cc;
        float Dg = lo16 ? r2v : dd;
        float s1in = b3 ? Ag : Bg;
        float s2in = b3 ? Cg : Dg;
        float e1 = __shfl_xor_sync(0xFFFFFFFFu, s1in, 8);
        float e2 = __shfl_xor_sync(0xFFFFFFFFu, s2in, 8);
        float iv = b3 ? e1 : Ag;
        float fv = b3 ? Bg : e1;
        float ov = b3 ? e2 : Cg;
        float zv = b3 ? Dg : e2;

        // state update: HW tanh.approx for z-tanh, output-sigmoid, and h-tanh
        float tz = tanh_hw(zv);
        float so = fmaf(tanh_hw(0.5f * ov), 0.5f, 0.5f);
        float lf = fminf(fv, 0.0f) - __logf(1.0f + __expf(-fabsf(fv)));
        float mn = fmaxf(lf + m_, iv);
        float ip = __expf(iv - mn);
        float fp = __expf(lf + m_ - mn);
        c_ = fp * c_ + ip * tz;
        n_ = fp * n_ + ip;
        m_ = mn;
        float hv = so * tanh_hw(__fdividef(c_, n_));

        hn[my_row * HH + my_hid] = hv;
        outp[0] = hv;
        outp += HH;

        p0 = q0; p1 = q1;
        __syncthreads();
    }
}

extern "C" void kernel_launch(void* const* d_in, const int* in_sizes, int n_in,
                              void* d_out, int out_size)
{
    const float* xg = (const float*)d_in[0];
    const float* Wm = (const float*)d_in[1];
    const float* Rm = (const float*)d_in[2];
    const float* bv = (const float*)d_in[3];
    if (n_in >= 3 && in_sizes[1] == HH * GG && in_sizes[2] == GG * II) {
        const float* t = Wm; Wm = Rm; Rm = t;
    }
    float* out = (float*)d_out;

    float* pre = nullptr;
    cudaGetSymbolAddress((void**)&pre, g_pre);

    cudaFuncSetAttribute(pre_gemm_persist,
                         cudaFuncAttributeMaxDynamicSharedMemorySize, GEMM_SMEM_BYTES);
    cudaFuncSetAttribute(slstm_scan_kernel,
                         cudaFuncAttributeMaxDynamicSharedMemorySize, SCAN_SMEM_BYTES);

    pre_gemm_persist<<<GEMM_CTAS, NTHR, GEMM_SMEM_BYTES>>>(xg, Wm, pre);
    slstm_scan_kernel<<<NCTA, NTHR, SCAN_SMEM_BYTES>>>(pre, Rm, bv, out);
}